// round 6
// baseline (speedup 1.0000x reference)
#include <cuda_runtime.h>

// HaarWavelet2D level=2, x:(8,64,256,256) fp32 -> (low,high) each same shape.
// One fused kernel, 64x32 output tile per 256-thread block.
// Shared memory uses even/odd column-split layouts so all stride-2 access
// patterns (Haar taps, 255->256 resize taps) are bank-conflict-free.
//
// smem map (floats):
//   xs  : x rows i0-3..i0+66 (70), cols j0-3..j0+34 (38) split E/O, stride 20
//   hs  : hi0 rows i0-1..i0+63 (65), cols j0-1..j0+31 (33) split E/O, stride 20
//   l1s/h1s : ll1/hi1 rows i0/2-1..i0/2+32 (34), cols j0/2-1..j0/2+16 (18), stride 24
// Epilogue: thread = 2 vertically adjacent 2x2 quads (4 rows x 2 cols out).

#define HW 256
#define IMG (HW*HW)
#define INV256 (1.0f/256.0f)

// smem offsets (floats). XO-XE = 1424 = 16 mod 32; HO-HE = 1328 = 16 mod 32.
#define XE_OFF 0
#define XO_OFF 1424
#define HE_OFF 2824
#define HO_OFF 4152
#define L1_OFF 5452
#define H1_OFF 6268
#define SM_TOT 7084

__device__ __forceinline__ int clampi(int v, int lo, int hi) {
    return v < lo ? lo : (v > hi ? hi : v);
}

__global__ void __launch_bounds__(256) k_fused(const float* __restrict__ x,
                                               float* __restrict__ out, int nc) {
    __shared__ float sm[SM_TOT];

    const int ch = blockIdx.z;
    const int i0 = blockIdx.y * 64;
    const int j0 = blockIdx.x * 32;
    const int tid = threadIdx.x;
    const float* xc = x + (size_t)ch * IMG;

    // column slot for x array (global col c in [max(0,j0-3), min(255,j0+34)])
#define XCOL(c) (((c) & 1) ? (XO_OFF + (((c) - j0 + 3) >> 1)) \
                           : (XE_OFF + (((c) - j0) >> 1) + 1))
    // column slot for hs array (global col t in [j0-1, j0+31])
#define HCOL(t) (((t) & 1) ? (HO_OFF + (((t) - j0 + 1) >> 1)) \
                           : (HE_OFF + (((t) - j0) >> 1)))

    // ---------------- stage 1: load x tile (halo 3), clamped ----------------
    for (int e = tid; e < 70 * 38; e += 256) {
        int u = e / 38, v = e - u * 38;
        int gr = clampi(i0 - 3 + u, 0, 255);
        int gc = clampi(j0 - 3 + v, 0, 255);
        sm[XCOL(gc) + u * 20] = __ldg(xc + gr * HW + gc);
    }
    __syncthreads();

    // ---------------- stage 2: hi0 tile ----------------
    // hs row u <-> hi0 row i0-1+u ; written at RAW column slot, values from
    // clamped x reads (edge slots hold garbage but are never read).
    for (int e = tid; e < 65 * 33; e += 256) {
        int u = e / 33, v = e - u * 33;
        int l = j0 - 1 + v;
        int lc = clampi(l, 0, 255);
        int lc1 = clampi(l + 1, 0, 255);
        int sa = XCOL(lc), sb = XCOL(lc1);
        int ra = (u + 2) * 20, rb = (u + 3) * 20;
        float a = sm[sa + ra], b = sm[sb + ra];
        float c = sm[sa + rb], d = sm[sb + rb];
        float lh = a + b - c - d;
        float hl = a - b + c - d;
        float hh = a - b - c + d;
        sm[HCOL(l) + u * 20] = 0.25f * (fabsf(lh) + fabsf(hl) + fabsf(hh));
    }

    // ---------------- stage 3: ll1 / hi1 directly from xs ----------------
    const int A0 = (i0 >> 1) - 1;   // l1 row-slot base (global ll1 row)
    const int B0 = (j0 >> 1) - 1;   // l1 col-slot base
    for (int e = tid; e < 34 * 18; e += 256) {
        int u = e / 18, v = e - u * 18;
        int a = clampi(A0 + u, 0, 127);
        int b = clampi(B0 + v, 0, 127);

        // x rows / cols (clamped taps)
        int r0 = max(2 * a - 1, 0), r1 = 2 * a, r2 = 2 * a + 1, r3 = min(2 * a + 2, 255);
        int c0 = max(2 * b - 1, 0), c1 = 2 * b, c2 = 2 * b + 1, c3 = min(2 * b + 2, 255);
        int s0 = XCOL(c0), s1 = XCOL(c1), s2 = XCOL(c2), s3 = XCOL(c3);
        bool bl = (b > 0), br = (b < 127);

        // per x-row column-pair sums for LL cols lm=max(2b-1,0), l0=2b, lp=min(2b+1,254)
        float cm0, cm1, cm2, cm3, cc0, cc1, cc2, cc3, cp0, cp1, cp2, cp3;
        {
            int rl;
            float x0, x1, x2, x3, s01, s12, s23;
#define ROWSUMS(IDX, RR)                                                     \
            rl = (RR) - (i0 - 3);                                            \
            x0 = sm[s0 + rl * 20]; x1 = sm[s1 + rl * 20];                    \
            x2 = sm[s2 + rl * 20]; x3 = sm[s3 + rl * 20];                    \
            s01 = x0 + x1; s12 = x1 + x2; s23 = x2 + x3;                     \
            cm##IDX = bl ? s01 : s12; cc##IDX = s12; cp##IDX = br ? s23 : s12;
            ROWSUMS(0, r0) ROWSUMS(1, r1) ROWSUMS(2, r2) ROWSUMS(3, r3)
#undef ROWSUMS
        }

        // LL rows: km uses x-rows (a>0 ? (0,1) : (1,2)); k0 = (1,2); kp = (a<127 ? (2,3) : (1,2))
        bool at = (a > 0), ab = (a < 127);
        float mA_m = at ? cm0 : cm1, mB_m = at ? cm1 : cm2;
        float mA_c = at ? cc0 : cc1, mB_c = at ? cc1 : cc2;
        float mA_p = at ? cp0 : cp1, mB_p = at ? cp1 : cp2;
        float pA_m = ab ? cm2 : cm1, pB_m = ab ? cm3 : cm2;
        float pA_c = ab ? cc2 : cc1, pB_c = ab ? cc3 : cc2;
        float pA_p = ab ? cp2 : cp1, pB_p = ab ? cp3 : cp2;

        float LLmm = 0.25f * (mA_m + mB_m), LLm0 = 0.25f * (mA_c + mB_c), LLmp = 0.25f * (mA_p + mB_p);
        float LL0m = 0.25f * (cm1 + cm2),   LL00 = 0.25f * (cc1 + cc2),   LL0p = 0.25f * (cp1 + cp2);
        float LLpm = 0.25f * (pA_m + pB_m), LLp0 = 0.25f * (pA_c + pB_c), LLpp = 0.25f * (pA_p + pB_p);

        float wy0 = (2 * a + 0.5f) * INV256;
        float wy1 = (2 * a + 1.5f) * INV256;
        float wx0 = (2 * b + 0.5f) * INV256;
        float wx1 = (2 * b + 1.5f) * INV256;

        float Am = wx0 * LLmm + (1.0f - wx0) * LLm0;
        float A0r = wx0 * LL0m + (1.0f - wx0) * LL00;
        float Ap = wx0 * LLpm + (1.0f - wx0) * LLp0;
        float Bm = wx1 * LLm0 + (1.0f - wx1) * LLmp;
        float B0r = wx1 * LL00 + (1.0f - wx1) * LL0p;
        float Bp = wx1 * LLp0 + (1.0f - wx1) * LLpp;

        float L00 = wy0 * Am + (1.0f - wy0) * A0r;
        float L01 = wy0 * Bm + (1.0f - wy0) * B0r;
        float L10 = wy1 * A0r + (1.0f - wy1) * Ap;
        float L11 = wy1 * B0r + (1.0f - wy1) * Bp;

        float ll = 0.25f * (L00 + L01 + L10 + L11);
        float lh = 0.25f * (L00 + L01 - L10 - L11);
        float hl = 0.25f * (L00 - L01 + L10 - L11);
        float hh = 0.25f * (L00 - L01 - L10 + L11);
        sm[L1_OFF + u * 24 + v] = ll;
        sm[H1_OFF + u * 24 + v] = fabsf(lh) + fabsf(hl) + fabsf(hh);
    }
    __syncthreads();

    // ---------------- stage 4: epilogue (2 vertical quads / thread) ----------------
    const int qx = tid & 15;
    const int ph = tid >> 4;              // 0..15
    const int q = (j0 >> 1) + qx;         // quad col  -> out cols 2q, 2q+1
    const int p0 = (i0 >> 1) + 2 * ph;    // first quad row -> out rows 2p0..2p0+3

    // --- hi0 resize: 5 rows x 3 cols of hs ---
    int g0 = max(2 * p0 - 1, 0);
    int g4 = min(2 * p0 + 3, 254);
    int hr0 = (g0 - i0 + 1) * 20;
    int hr1 = (2 * p0 - i0 + 1) * 20;
    int hr2 = hr1 + 20, hr3 = hr1 + 40;
    int hr4 = (g4 - i0 + 1) * 20;
    int tm = max(2 * q - 1, 0), t0c = 2 * q, tp = min(2 * q + 1, 254);
    int hm = HCOL(tm), hc = HCOL(t0c), hp = HCOL(tp);

    float wx0 = (2 * q + 0.5f) * INV256;
    float wx1 = (2 * q + 1.5f) * INV256;

    float cA0 = wx0 * sm[hm + hr0] + (1.0f - wx0) * sm[hc + hr0];
    float cA1 = wx0 * sm[hm + hr1] + (1.0f - wx0) * sm[hc + hr1];
    float cA2 = wx0 * sm[hm + hr2] + (1.0f - wx0) * sm[hc + hr2];
    float cA3 = wx0 * sm[hm + hr3] + (1.0f - wx0) * sm[hc + hr3];
    float cA4 = wx0 * sm[hm + hr4] + (1.0f - wx0) * sm[hc + hr4];
    float cB0 = wx1 * sm[hc + hr0] + (1.0f - wx1) * sm[hp + hr0];
    float cB1 = wx1 * sm[hc + hr1] + (1.0f - wx1) * sm[hp + hr1];
    float cB2 = wx1 * sm[hc + hr2] + (1.0f - wx1) * sm[hp + hr2];
    float cB3 = wx1 * sm[hc + hr3] + (1.0f - wx1) * sm[hp + hr3];
    float cB4 = wx1 * sm[hc + hr4] + (1.0f - wx1) * sm[hp + hr4];

    float wy0 = (2 * p0 + 0.5f) * INV256;
    float wy1 = (2 * p0 + 1.5f) * INV256;
    float wy2 = (2 * p0 + 2.5f) * INV256;
    float wy3 = (2 * p0 + 3.5f) * INV256;

    float h0A0 = wy0 * cA0 + (1.0f - wy0) * cA1;
    float h0B0 = wy0 * cB0 + (1.0f - wy0) * cB1;
    float h0A1 = wy1 * cA1 + (1.0f - wy1) * cA2;
    float h0B1 = wy1 * cB1 + (1.0f - wy1) * cB2;
    float h0A2 = wy2 * cA2 + (1.0f - wy2) * cA3;
    float h0B2 = wy2 * cB2 + (1.0f - wy2) * cB3;
    float h0A3 = wy3 * cA3 + (1.0f - wy3) * cA4;
    float h0B3 = wy3 * cB3 + (1.0f - wy3) * cB4;

    // --- ll1 / hi1 resize: 4 rows x 3 cols each ---
    const int A0b = (i0 >> 1) - 1;
    const int B0b = (j0 >> 1) - 1;
    int e0 = (max(p0 - 1, 0) - A0b) * 24;
    int e1 = (p0 - A0b) * 24;
    int e2 = e1 + 24;
    int e3 = (min(p0 + 2, 127) - A0b) * 24;
    int f0 = max(q - 1, 0) - B0b;
    int f1 = q - B0b;
    int f2 = min(q + 1, 127) - B0b;

#define RESIZE128(BASE, oA0, oB0, oA1, oB1, oA2, oB2, oA3, oB3)               \
    {                                                                         \
        float r0m = sm[BASE + e0 + f0], r0c = sm[BASE + e0 + f1], r0p = sm[BASE + e0 + f2]; \
        float r1m = sm[BASE + e1 + f0], r1c = sm[BASE + e1 + f1], r1p = sm[BASE + e1 + f2]; \
        float r2m = sm[BASE + e2 + f0], r2c = sm[BASE + e2 + f1], r2p = sm[BASE + e2 + f2]; \
        float r3m = sm[BASE + e3 + f0], r3c = sm[BASE + e3 + f1], r3p = sm[BASE + e3 + f2]; \
        float a0 = 0.25f * r0m + 0.75f * r0c, b0 = 0.75f * r0c + 0.25f * r0p; \
        float a1 = 0.25f * r1m + 0.75f * r1c, b1 = 0.75f * r1c + 0.25f * r1p; \
        float a2 = 0.25f * r2m + 0.75f * r2c, b2 = 0.75f * r2c + 0.25f * r2p; \
        float a3 = 0.25f * r3m + 0.75f * r3c, b3 = 0.75f * r3c + 0.25f * r3p; \
        oA0 = 0.25f * a0 + 0.75f * a1; oB0 = 0.25f * b0 + 0.75f * b1;         \
        oA1 = 0.75f * a1 + 0.25f * a2; oB1 = 0.75f * b1 + 0.25f * b2;         \
        oA2 = 0.25f * a1 + 0.75f * a2; oB2 = 0.25f * b1 + 0.75f * b2;         \
        oA3 = 0.75f * a2 + 0.25f * a3; oB3 = 0.75f * b2 + 0.25f * b3;         \
    }

    float loA0, loB0, loA1, loB1, loA2, loB2, loA3, loB3;
    RESIZE128(L1_OFF, loA0, loB0, loA1, loB1, loA2, loB2, loA3, loB3)
    float h1A0, h1B0, h1A1, h1B1, h1A2, h1B2, h1A3, h1B3;
    RESIZE128(H1_OFF, h1A0, h1B0, h1A1, h1B1, h1A2, h1B2, h1A3, h1B3)
#undef RESIZE128

    // --- stores: rows 2p0..2p0+3, cols 2q..2q+1, float2 ---
    const size_t nimg = (size_t)nc * IMG;
    float* out_low = out;
    float* out_high = out + nimg;
    size_t base = (size_t)ch * IMG + (size_t)(2 * p0) * HW + 2 * q;

    *reinterpret_cast<float2*>(out_low + base) = make_float2(loA0, loB0);
    *reinterpret_cast<float2*>(out_low + base + HW) = make_float2(loA1, loB1);
    *reinterpret_cast<float2*>(out_low + base + 2 * HW) = make_float2(loA2, loB2);
    *reinterpret_cast<float2*>(out_low + base + 3 * HW) = make_float2(loA3, loB3);
    *reinterpret_cast<float2*>(out_high + base) =
        make_float2(0.5f * (h0A0 + h1A0), 0.5f * (h0B0 + h1B0));
    *reinterpret_cast<float2*>(out_high + base + HW) =
        make_float2(0.5f * (h0A1 + h1A1), 0.5f * (h0B1 + h1B1));
    *reinterpret_cast<float2*>(out_high + base + 2 * HW) =
        make_float2(0.5f * (h0A2 + h1A2), 0.5f * (h0B2 + h1B2));
    *reinterpret_cast<float2*>(out_high + base + 3 * HW) =
        make_float2(0.5f * (h0A3 + h1A3), 0.5f * (h0B3 + h1B3));
}

extern "C" void kernel_launch(void* const* d_in, const int* in_sizes, int n_in,
                              void* d_out, int out_size) {
    const float* x = (const float*)d_in[0];
    float* out = (float*)d_out;
    int nc = in_sizes[0] / IMG;  // 512

    dim3 blk(256);
    dim3 grd(HW / 32, HW / 64, nc);
    k_fused<<<grd, blk>>>(x, out, nc);
}

// round 7
// speedup vs baseline: 1.1332x; 1.1332x over previous
#include <cuda_runtime.h>

// HaarWavelet2D level=2, x:(8,64,256,256) fp32 -> (low,high).
// One fused kernel, 64x32 output tile per 256-thread block.
// All smem arrays use even/odd column split (conflict-free stride-2) with
// PURE virtual-slot indexing; image-edge correctness comes from clamp-at-load
// plus a reflect patch (virtual col -1 -> 1, 256 -> 254) in stage 1.
//
// Arrays (floats, strides chosen for epilogue bank disjointness):
//   xsE/xsO : x rows i0-3..i0+66 (70), E cols j0-2+2w / O cols j0-3+2w (19 each), stride 20
//   LLE/LLO : ll0 rows i0-3..i0+65 (69), same col mapping (18/19 used), stride 20
//   hsE/hsO : hi0 rows i0-1..i0+63 (65), E cols j0+2w (16) / O cols j0-1+2w (17), stride 20
//   l1s/h1s : ll1/hi1, rows a=clamp(i0/2-1+u) (34), cols b=clamp(j0/2-1+v) (18), stride 24
// Epilogue: thread = 2 vertical 2x2 quads (4 out rows x 2 out cols).

#define HW 256
#define IMG (HW*HW)
#define INV256 (1.0f/256.0f)

// smem offsets (floats). XO-XE = 1424 ≡ 16 (mod 32) for the split stage-1 STS.
#define XE 0
#define XO 1424
#define LLE 2848
#define LLO 4228
#define HSE 5608
#define HSO 6908
#define L1S 8208
#define H1S 9024
#define SM_TOT 9840

__device__ __forceinline__ int clampi(int v, int lo, int hi) {
    return v < lo ? lo : (v > hi ? hi : v);
}

__global__ void __launch_bounds__(256) k_fused(const float* __restrict__ x,
                                               float* __restrict__ out, int nc) {
    __shared__ float sm[SM_TOT];

    const int ch = blockIdx.z;
    const int i0 = blockIdx.y * 64;
    const int j0 = blockIdx.x * 32;
    const int tid = threadIdx.x;
    const float* xc = x + (size_t)ch * IMG;

    // ---------------- stage 1: load x (70 rows x 38 cols) ----------------
    for (int e = tid; e < 70 * 38; e += 256) {
        int u = e / 38, v = e - u * 38;
        int gr = clampi(i0 - 3 + u, 0, 255);
        int g = j0 - 3 + v;
        int gc = clampi(g, 0, 255);
        if (g == -1) gc = 1;        // reflect patch (left edge)
        if (g == 256) gc = 254;     // reflect patch (right edge)
        float val = __ldg(xc + gr * HW + gc);
        // v even -> global col odd -> xsO slot v/2 ; v odd -> xsE slot v>>1
        sm[((v & 1) ? XE : XO) + u * 20 + (v >> 1)] = val;
    }
    __syncthreads();

    // ---------------- stage 2: LL (ll0) + hi0, shared reads ----------------
    // iteration (r, w): LLO[r][w] from (xsO[w], xsE[w]); LLE[r][w] (w<=17)
    // from (xsE[w], xsO[w+1]); hi0 stored for interior hs range.
    for (int e = tid; e < 69 * 19; e += 256) {
        int r = e / 19, w = e - r * 19;
        int ro = r * 20, r1 = ro + 20;
        float o0 = sm[XO + ro + w], e0 = sm[XE + ro + w];
        float o1 = sm[XO + r1 + w], e1 = sm[XE + r1 + w];

        // LLO point (cols cO, cO+1)
        float sA = o0 + e0, dA = o0 - e0;
        float sB = o1 + e1, dB = o1 - e1;
        sm[LLO + ro + w] = 0.25f * (sA + sB);
        bool hrow = (r >= 2) && (r <= 66);
        int hb = (r - 2) * 20;
        if (hrow && w >= 1 && w <= 17)
            sm[HSO + hb + (w - 1)] =
                0.25f * (fabsf(sA - sB) + fabsf(dA + dB) + fabsf(dA - dB));

        if (w <= 17) {
            float p0 = sm[XO + ro + w + 1];
            float p1 = sm[XO + r1 + w + 1];
            // LLE point (cols cE, cE+1)
            float sC = e0 + p0, dC = e0 - p0;
            float sD = e1 + p1, dD = e1 - p1;
            sm[LLE + ro + w] = 0.25f * (sC + sD);
            if (hrow && w >= 1)
                sm[HSE + hb + (w - 1)] =
                    0.25f * (fabsf(sC - sD) + fabsf(dC + dD) + fabsf(dC - dD));
        }
    }
    __syncthreads();

    // ---------------- stage 3: ll1 / hi1 from LL arrays ----------------
    const int A0 = (i0 >> 1) - 1;
    const int B0 = (j0 >> 1) - 1;
    for (int e = tid; e < 34 * 18; e += 256) {
        int u = e / 18, v = e - u * 18;
        int a = clampi(A0 + u, 0, 127);
        int b = clampi(B0 + v, 0, 127);
        int d = b - B0;
        int rm = (clampi(2 * a - 1, 0, 254) - (i0 - 3)) * 20;
        int r0 = (2 * a - (i0 - 3)) * 20;
        int rp = (clampi(2 * a + 1, 0, 254) - (i0 - 3)) * 20;

        float m_m = sm[LLO + rm + d], m_0 = sm[LLE + rm + d], m_p = sm[LLO + rm + d + 1];
        float c_m = sm[LLO + r0 + d], c_0 = sm[LLE + r0 + d], c_p = sm[LLO + r0 + d + 1];
        float p_m = sm[LLO + rp + d], p_0 = sm[LLE + rp + d], p_p = sm[LLO + rp + d + 1];

        float wy0 = (2 * a + 0.5f) * INV256, wy1 = (2 * a + 1.5f) * INV256;
        float wx0 = (2 * b + 0.5f) * INV256, wx1 = (2 * b + 1.5f) * INV256;

        float Am = wx0 * m_m + (1.0f - wx0) * m_0;
        float Ac = wx0 * c_m + (1.0f - wx0) * c_0;
        float Ap = wx0 * p_m + (1.0f - wx0) * p_0;
        float Bm = wx1 * m_0 + (1.0f - wx1) * m_p;
        float Bc = wx1 * c_0 + (1.0f - wx1) * c_p;
        float Bp = wx1 * p_0 + (1.0f - wx1) * p_p;

        float L00 = wy0 * Am + (1.0f - wy0) * Ac;
        float L01 = wy0 * Bm + (1.0f - wy0) * Bc;
        float L10 = wy1 * Ac + (1.0f - wy1) * Ap;
        float L11 = wy1 * Bc + (1.0f - wy1) * Bp;

        float ll = 0.25f * (L00 + L01 + L10 + L11);
        float lh = 0.25f * (L00 + L01 - L10 - L11);
        float hl = 0.25f * (L00 - L01 + L10 - L11);
        float hh = 0.25f * (L00 - L01 - L10 + L11);
        sm[L1S + u * 24 + v] = ll;
        sm[H1S + u * 24 + v] = fabsf(lh) + fabsf(hl) + fabsf(hh);
    }
    __syncthreads();

    // ---------------- stage 4: epilogue (2 vertical quads / thread) ----------------
    const int qx = tid & 15;
    const int ph = tid >> 4;                 // 0..15
    const int q = (j0 >> 1) + qx;            // out cols 2q, 2q+1
    const int p0 = (i0 >> 1) + 2 * ph;       // out rows 2p0..2p0+3

    // --- hi0 resize (255->256): 5 rows x 3 cols, only 2 row clamps ---
    int s0 = (clampi(2 * p0 - 1, 0, 254) - (i0 - 1)) * 20;
    int s1 = (4 * ph + 1) * 20;
    int s2 = s1 + 20, s3 = s1 + 40;
    int s4 = (clampi(2 * p0 + 3, 0, 254) - (i0 - 1)) * 20;

    float w0 = (2 * q + 0.5f) * INV256;
    float w1 = (2 * q + 1.5f) * INV256;

#define HCL(S, CA, CB)                                                        \
    {                                                                         \
        float ov = sm[HSO + (S) + qx], ev = sm[HSE + (S) + qx];               \
        float o2 = sm[HSO + (S) + qx + 1];                                    \
        CA = w0 * ov + (1.0f - w0) * ev;                                      \
        CB = w1 * ev + (1.0f - w1) * o2;                                      \
    }
    float cA0, cB0, cA1, cB1, cA2, cB2, cA3, cB3, cA4, cB4;
    HCL(s0, cA0, cB0) HCL(s1, cA1, cB1) HCL(s2, cA2, cB2)
    HCL(s3, cA3, cB3) HCL(s4, cA4, cB4)
#undef HCL

    float wy0 = (2 * p0 + 0.5f) * INV256;
    float wy1 = (2 * p0 + 1.5f) * INV256;
    float wy2 = (2 * p0 + 2.5f) * INV256;
    float wy3 = (2 * p0 + 3.5f) * INV256;

    float h0A0 = wy0 * cA0 + (1.0f - wy0) * cA1;
    float h0B0 = wy0 * cB0 + (1.0f - wy0) * cB1;
    float h0A1 = wy1 * cA1 + (1.0f - wy1) * cA2;
    float h0B1 = wy1 * cB1 + (1.0f - wy1) * cB2;
    float h0A2 = wy2 * cA2 + (1.0f - wy2) * cA3;
    float h0B2 = wy2 * cB2 + (1.0f - wy2) * cB3;
    float h0A3 = wy3 * cA3 + (1.0f - wy3) * cA4;
    float h0B3 = wy3 * cB3 + (1.0f - wy3) * cB4;

    // --- ll1/hi1 resize (128->256): 4 rows x 3 cols each, clamp-free ---
    int t0 = 2 * ph * 24;
    int t1 = t0 + 24, t2 = t0 + 48, t3 = t0 + 72;

#define RESIZE128(BASE, oA0, oB0, oA1, oB1, oA2, oB2, oA3, oB3)               \
    {                                                                         \
        float r0m = sm[BASE + t0 + qx], r0c = sm[BASE + t0 + qx + 1], r0p = sm[BASE + t0 + qx + 2]; \
        float r1m = sm[BASE + t1 + qx], r1c = sm[BASE + t1 + qx + 1], r1p = sm[BASE + t1 + qx + 2]; \
        float r2m = sm[BASE + t2 + qx], r2c = sm[BASE + t2 + qx + 1], r2p = sm[BASE + t2 + qx + 2]; \
        float r3m = sm[BASE + t3 + qx], r3c = sm[BASE + t3 + qx + 1], r3p = sm[BASE + t3 + qx + 2]; \
        float a0 = 0.25f * r0m + 0.75f * r0c, b0 = 0.75f * r0c + 0.25f * r0p; \
        float a1 = 0.25f * r1m + 0.75f * r1c, b1 = 0.75f * r1c + 0.25f * r1p; \
        float a2 = 0.25f * r2m + 0.75f * r2c, b2 = 0.75f * r2c + 0.25f * r2p; \
        float a3 = 0.25f * r3m + 0.75f * r3c, b3 = 0.75f * r3c + 0.25f * r3p; \
        oA0 = 0.25f * a0 + 0.75f * a1; oB0 = 0.25f * b0 + 0.75f * b1;         \
        oA1 = 0.75f * a1 + 0.25f * a2; oB1 = 0.75f * b1 + 0.25f * b2;         \
        oA2 = 0.25f * a1 + 0.75f * a2; oB2 = 0.25f * b1 + 0.75f * b2;         \
        oA3 = 0.75f * a2 + 0.25f * a3; oB3 = 0.75f * b2 + 0.25f * b3;         \
    }

    float loA0, loB0, loA1, loB1, loA2, loB2, loA3, loB3;
    RESIZE128(L1S, loA0, loB0, loA1, loB1, loA2, loB2, loA3, loB3)
    float h1A0, h1B0, h1A1, h1B1, h1A2, h1B2, h1A3, h1B3;
    RESIZE128(H1S, h1A0, h1B0, h1A1, h1B1, h1A2, h1B2, h1A3, h1B3)
#undef RESIZE128

    // --- stores: rows 2p0..2p0+3, cols 2q..2q+1 ---
    const size_t nimg = (size_t)nc * IMG;
    float* out_low = out;
    float* out_high = out + nimg;
    size_t base = (size_t)ch * IMG + (size_t)(2 * p0) * HW + 2 * q;

    *reinterpret_cast<float2*>(out_low + base) = make_float2(loA0, loB0);
    *reinterpret_cast<float2*>(out_low + base + HW) = make_float2(loA1, loB1);
    *reinterpret_cast<float2*>(out_low + base + 2 * HW) = make_float2(loA2, loB2);
    *reinterpret_cast<float2*>(out_low + base + 3 * HW) = make_float2(loA3, loB3);
    *reinterpret_cast<float2*>(out_high + base) =
        make_float2(0.5f * (h0A0 + h1A0), 0.5f * (h0B0 + h1B0));
    *reinterpret_cast<float2*>(out_high + base + HW) =
        make_float2(0.5f * (h0A1 + h1A1), 0.5f * (h0B1 + h1B1));
    *reinterpret_cast<float2*>(out_high + base + 2 * HW) =
        make_float2(0.5f * (h0A2 + h1A2), 0.5f * (h0B2 + h1B2));
    *reinterpret_cast<float2*>(out_high + base + 3 * HW) =
        make_float2(0.5f * (h0A3 + h1A3), 0.5f * (h0B3 + h1B3));
}

extern "C" void kernel_launch(void* const* d_in, const int* in_sizes, int n_in,
                              void* d_out, int out_size) {
    const float* x = (const float*)d_in[0];
    float* out = (float*)d_out;
    int nc = in_sizes[0] / IMG;  // 512

    dim3 blk(256);
    dim3 grd(HW / 32, HW / 64, nc);
    k_fused<<<grd, blk>>>(x, out, nc);
}

// round 11
// speedup vs baseline: 1.2312x; 1.0865x over previous
#include <cuda_runtime.h>

// HaarWavelet2D level=2, x:(8,64,256,256) fp32 -> (low,high).
// One fused kernel, 64x32 output tile per 256-thread block.
// E/O column-split smem (conflict-free stride-2), clamp-at-load + reflect
// patch (virtual col -1 -> 1, 256 -> 254) for pure downstream indexing.
// ll1/hi1 stored interleaved as float2 -> epilogue uses LDS.64.
// __launch_bounds__(256,6): 40 regs + 37.7KB smem -> 6 CTAs/SM.

#define HW 256
#define IMG (HW*HW)
#define INV256 (1.0f/256.0f)

// smem offsets (floats). XO-XE = 1424 ≡ 16 (mod 32) for split stage-1 STS.
#define XE 0
#define XO 1424
#define LLE 2848
#define LLO 4228
#define HSE 5608
#define HSO 6908
#define L12 8208            // interleaved {ll1, hi1}: 34 rows x 18 float2
#define SM_TOT 9432

__device__ __forceinline__ int clampi(int v, int lo, int hi) {
    return v < lo ? lo : (v > hi ? hi : v);
}

__global__ void __launch_bounds__(256, 6) k_fused(const float* __restrict__ x,
                                                  float* __restrict__ out, int nc) {
    __shared__ float sm[SM_TOT];

    const int ch = blockIdx.z;
    const int i0 = blockIdx.y * 64;
    const int j0 = blockIdx.x * 32;
    const int tid = threadIdx.x;
    const float* xc = x + (size_t)ch * IMG;

    // ---------------- stage 1: load x (70 rows x 38 cols) ----------------
    for (int e = tid; e < 70 * 38; e += 256) {
        int u = e / 38, v = e - u * 38;
        int gr = clampi(i0 - 3 + u, 0, 255);
        int g = j0 - 3 + v;
        int gc = clampi(g, 0, 255);
        if (g == -1) gc = 1;        // reflect patch (left edge)
        if (g == 256) gc = 254;     // reflect patch (right edge)
        float val = __ldg(xc + gr * HW + gc);
        // v even -> global col odd -> xsO slot v/2 ; v odd -> xsE slot v>>1
        sm[((v & 1) ? XE : XO) + u * 20 + (v >> 1)] = val;
    }
    __syncthreads();

    // ---------------- stage 2: LL (ll0) + hi0, shared reads ----------------
    for (int e = tid; e < 69 * 19; e += 256) {
        int r = e / 19, w = e - r * 19;
        int ro = r * 20, r1 = ro + 20;
        float o0 = sm[XO + ro + w], e0 = sm[XE + ro + w];
        float o1 = sm[XO + r1 + w], e1 = sm[XE + r1 + w];

        // LLO point (cols cO, cO+1)
        float sA = o0 + e0, dA = o0 - e0;
        float sB = o1 + e1, dB = o1 - e1;
        sm[LLO + ro + w] = 0.25f * (sA + sB);
        bool hrow = (r >= 2) && (r <= 66);
        int hb = (r - 2) * 20;
        if (hrow && w >= 1 && w <= 17)
            sm[HSO + hb + (w - 1)] =
                0.25f * (fabsf(sA - sB) + fabsf(dA + dB) + fabsf(dA - dB));

        if (w <= 17) {
            float p0 = sm[XO + ro + w + 1];
            float p1 = sm[XO + r1 + w + 1];
            // LLE point (cols cE, cE+1)
            float sC = e0 + p0, dC = e0 - p0;
            float sD = e1 + p1, dD = e1 - p1;
            sm[LLE + ro + w] = 0.25f * (sC + sD);
            if (hrow && w >= 1)
                sm[HSE + hb + (w - 1)] =
                    0.25f * (fabsf(sC - sD) + fabsf(dC + dD) + fabsf(dC - dD));
        }
    }
    __syncthreads();

    // ---------------- stage 3: ll1 / hi1 from LL arrays ----------------
    const int A0 = (i0 >> 1) - 1;
    const int B0 = (j0 >> 1) - 1;
    float2* l12 = reinterpret_cast<float2*>(sm + L12);
    for (int e = tid; e < 34 * 18; e += 256) {
        int u = e / 18, v = e - u * 18;
        int a = clampi(A0 + u, 0, 127);
        int b = clampi(B0 + v, 0, 127);
        int d = b - B0;
        int rm = (clampi(2 * a - 1, 0, 254) - (i0 - 3)) * 20;
        int r0 = (2 * a - (i0 - 3)) * 20;
        int rp = (clampi(2 * a + 1, 0, 254) - (i0 - 3)) * 20;

        float m_m = sm[LLO + rm + d], m_0 = sm[LLE + rm + d], m_p = sm[LLO + rm + d + 1];
        float c_m = sm[LLO + r0 + d], c_0 = sm[LLE + r0 + d], c_p = sm[LLO + r0 + d + 1];
        float p_m = sm[LLO + rp + d], p_0 = sm[LLE + rp + d], p_p = sm[LLO + rp + d + 1];

        float wy0 = (2 * a + 0.5f) * INV256, wy1 = (2 * a + 1.5f) * INV256;
        float wx0 = (2 * b + 0.5f) * INV256, wx1 = (2 * b + 1.5f) * INV256;

        float Am = wx0 * m_m + (1.0f - wx0) * m_0;
        float Ac = wx0 * c_m + (1.0f - wx0) * c_0;
        float Ap = wx0 * p_m + (1.0f - wx0) * p_0;
        float Bm = wx1 * m_0 + (1.0f - wx1) * m_p;
        float Bc = wx1 * c_0 + (1.0f - wx1) * c_p;
        float Bp = wx1 * p_0 + (1.0f - wx1) * p_p;

        float L00 = wy0 * Am + (1.0f - wy0) * Ac;
        float L01 = wy0 * Bm + (1.0f - wy0) * Bc;
        float L10 = wy1 * Ac + (1.0f - wy1) * Ap;
        float L11 = wy1 * Bc + (1.0f - wy1) * Bp;

        float ll = 0.25f * (L00 + L01 + L10 + L11);
        float lh = 0.25f * (L00 + L01 - L10 - L11);
        float hl = 0.25f * (L00 - L01 + L10 - L11);
        float hh = 0.25f * (L00 - L01 - L10 + L11);
        l12[u * 18 + v] = make_float2(ll, fabsf(lh) + fabsf(hl) + fabsf(hh));
    }
    __syncthreads();

    // ---------------- stage 4: epilogue (2 vertical quads / thread) ----------------
    const int qx = tid & 15;
    const int ph = tid >> 4;                 // 0..15
    const int q = (j0 >> 1) + qx;            // out cols 2q, 2q+1
    const int p0 = (i0 >> 1) + 2 * ph;       // out rows 2p0..2p0+3

    // --- hi0 resize (255->256): 5 rows x 3 cols, only 2 row clamps ---
    int s0 = (clampi(2 * p0 - 1, 0, 254) - (i0 - 1)) * 20;
    int s1 = (4 * ph + 1) * 20;
    int s2 = s1 + 20, s3 = s1 + 40;
    int s4 = (clampi(2 * p0 + 3, 0, 254) - (i0 - 1)) * 20;

    float w0 = (2 * q + 0.5f) * INV256;
    float w1 = (2 * q + 1.5f) * INV256;

#define HCL(S, CA, CB)                                                        \
    {                                                                         \
        float ov = sm[HSO + (S) + qx], ev = sm[HSE + (S) + qx];               \
        float o2 = sm[HSO + (S) + qx + 1];                                    \
        CA = w0 * ov + (1.0f - w0) * ev;                                      \
        CB = w1 * ev + (1.0f - w1) * o2;                                      \
    }
    float cA0, cB0, cA1, cB1, cA2, cB2, cA3, cB3, cA4, cB4;
    HCL(s0, cA0, cB0) HCL(s1, cA1, cB1) HCL(s2, cA2, cB2)
    HCL(s3, cA3, cB3) HCL(s4, cA4, cB4)
#undef HCL

    float wy0 = (2 * p0 + 0.5f) * INV256;
    float wy1 = (2 * p0 + 1.5f) * INV256;
    float wy2 = (2 * p0 + 2.5f) * INV256;
    float wy3 = (2 * p0 + 3.5f) * INV256;

    float h0A0 = wy0 * cA0 + (1.0f - wy0) * cA1;
    float h0B0 = wy0 * cB0 + (1.0f - wy0) * cB1;
    float h0A1 = wy1 * cA1 + (1.0f - wy1) * cA2;
    float h0B1 = wy1 * cB1 + (1.0f - wy1) * cB2;
    float h0A2 = wy2 * cA2 + (1.0f - wy2) * cA3;
    float h0B2 = wy2 * cB2 + (1.0f - wy2) * cB3;
    float h0A3 = wy3 * cA3 + (1.0f - wy3) * cA4;
    float h0B3 = wy3 * cB3 + (1.0f - wy3) * cB4;

    // --- ll1/hi1 resize (128->256): float2 taps, 4 rows x 3 cols, pure ---
    const float2* l12c = reinterpret_cast<const float2*>(sm + L12);
    int t0 = 2 * ph * 18 + qx;
    int t1 = t0 + 18, t2 = t0 + 36, t3 = t0 + 54;

#define LERP2(O, WA, A, WB, B)                                                \
    { O.x = (WA) * A.x + (WB) * B.x; O.y = (WA) * A.y + (WB) * B.y; }

    float2 r0m = l12c[t0], r0c = l12c[t0 + 1], r0p = l12c[t0 + 2];
    float2 r1m = l12c[t1], r1c = l12c[t1 + 1], r1p = l12c[t1 + 2];
    float2 r2m = l12c[t2], r2c = l12c[t2 + 1], r2p = l12c[t2 + 2];
    float2 r3m = l12c[t3], r3c = l12c[t3 + 1], r3p = l12c[t3 + 2];

    float2 a0, b0, a1, b1, a2, b2, a3, b3;
    LERP2(a0, 0.25f, r0m, 0.75f, r0c) LERP2(b0, 0.75f, r0c, 0.25f, r0p)
    LERP2(a1, 0.25f, r1m, 0.75f, r1c) LERP2(b1, 0.75f, r1c, 0.25f, r1p)
    LERP2(a2, 0.25f, r2m, 0.75f, r2c) LERP2(b2, 0.75f, r2c, 0.25f, r2p)
    LERP2(a3, 0.25f, r3m, 0.75f, r3c) LERP2(b3, 0.75f, r3c, 0.25f, r3p)

    float2 vA0, vB0, vA1, vB1, vA2, vB2, vA3, vB3;
    LERP2(vA0, 0.25f, a0, 0.75f, a1) LERP2(vB0, 0.25f, b0, 0.75f, b1)
    LERP2(vA1, 0.75f, a1, 0.25f, a2) LERP2(vB1, 0.75f, b1, 0.25f, b2)
    LERP2(vA2, 0.25f, a1, 0.75f, a2) LERP2(vB2, 0.25f, b1, 0.75f, b2)
    LERP2(vA3, 0.75f, a2, 0.25f, a3) LERP2(vB3, 0.75f, b2, 0.25f, b3)
#undef LERP2

    // --- stores: rows 2p0..2p0+3, cols 2q..2q+1 ---
    const size_t nimg = (size_t)nc * IMG;
    float* out_low = out;
    float* out_high = out + nimg;
    size_t base = (size_t)ch * IMG + (size_t)(2 * p0) * HW + 2 * q;

    *reinterpret_cast<float2*>(out_low + base) = make_float2(vA0.x, vB0.x);
    *reinterpret_cast<float2*>(out_low + base + HW) = make_float2(vA1.x, vB1.x);
    *reinterpret_cast<float2*>(out_low + base + 2 * HW) = make_float2(vA2.x, vB2.x);
    *reinterpret_cast<float2*>(out_low + base + 3 * HW) = make_float2(vA3.x, vB3.x);
    *reinterpret_cast<float2*>(out_high + base) =
        make_float2(0.5f * (h0A0 + vA0.y), 0.5f * (h0B0 + vB0.y));
    *reinterpret_cast<float2*>(out_high + base + HW) =
        make_float2(0.5f * (h0A1 + vA1.y), 0.5f * (h0B1 + vB1.y));
    *reinterpret_cast<float2*>(out_high + base + 2 * HW) =
        make_float2(0.5f * (h0A2 + vA2.y), 0.5f * (h0B2 + vB2.y));
    *reinterpret_cast<float2*>(out_high + base + 3 * HW) =
        make_float2(0.5f * (h0A3 + vA3.y), 0.5f * (h0B3 + vB3.y));
}

extern "C" void kernel_launch(void* const* d_in, const int* in_sizes, int n_in,
                              void* d_out, int out_size) {
    const float* x = (const float*)d_in[0];
    float* out = (float*)d_out;
    int nc = in_sizes[0] / IMG;  // 512

    dim3 blk(256);
    dim3 grd(HW / 32, HW / 64, nc);
    k_fused<<<grd, blk>>>(x, out, nc);
}

// round 12
// speedup vs baseline: 1.5351x; 1.2469x over previous
#include <cuda_runtime.h>

// HaarWavelet2D level=2, x:(8,64,256,256) fp32 -> (low,high).
// One fused kernel, 64x32 output tile per 256-thread block.
// E/O column-split smem (conflict-free stride-2), clamp-at-load + reflect
// patch for pure downstream indexing. ll1/hi1 interleaved float2 (LDS.64),
// OVERLAID on the xs region (dead after stage 2) -> 32.8KB smem, 7 CTAs/SM.
// Stage 1 uses float2 global loads on interior block columns.
//
// XE: even cols j0-4..j0+34 -> slots 0..19 (slot (c-j0+4)/2), stride 20
// XO: odd  cols j0-3..j0+35 -> slots 0..19 (slot (c-j0+3)/2), stride 20

#define HW 256
#define IMG (HW*HW)
#define INV256 (1.0f/256.0f)

// smem offsets (floats). XO-XE = 1424 ≡ 16 (mod 32).
#define XE 0
#define XO 1424
#define LLE 2848
#define LLO 4228
#define HSE 5608
#define HSO 6908
#define L12 0              // interleaved {ll1,hi1} float2, ALIASES xs region
#define SM_TOT 8208

__device__ __forceinline__ int clampi(int v, int lo, int hi) {
    return v < lo ? lo : (v > hi ? hi : v);
}

__global__ void __launch_bounds__(256, 7) k_fused(const float* __restrict__ x,
                                                  float* __restrict__ out, int nc) {
    __shared__ float sm[SM_TOT];

    const int ch = blockIdx.z;
    const int i0 = blockIdx.y * 64;
    const int j0 = blockIdx.x * 32;
    const int tid = threadIdx.x;
    const float* xc = x + (size_t)ch * IMG;

    // ---------------- stage 1: load x ----------------
    if (blockIdx.x != 0 && blockIdx.x != 7) {
        // interior: cols j0-4..j0+35 all in [0,255]; float2 loads (8B aligned).
        for (int e = tid; e < 70 * 20; e += 256) {
            int u = e / 20, m = e - u * 20;
            int gr = clampi(i0 - 3 + u, 0, 255);
            float2 v2 = *reinterpret_cast<const float2*>(xc + gr * HW + (j0 - 4 + 2 * m));
            sm[XE + u * 20 + m] = v2.x;   // even col j0-4+2m
            sm[XO + u * 20 + m] = v2.y;   // odd  col j0-3+2m
        }
    } else {
        // edge blocks: scalar with clamp + reflect patch.
        for (int e = tid; e < 70 * 38; e += 256) {
            int u = e / 38, v = e - u * 38;
            int gr = clampi(i0 - 3 + u, 0, 255);
            int g = j0 - 3 + v;
            int gc = clampi(g, 0, 255);
            if (g == -1) gc = 1;
            if (g == 256) gc = 254;
            float val = __ldg(xc + gr * HW + gc);
            // v odd -> even col g -> XE slot (v>>1)+1 ; v even -> odd col -> XO slot v>>1
            sm[((v & 1) ? (XE + 1) : XO) + u * 20 + (v >> 1)] = val;
        }
    }
    __syncthreads();

    // ---------------- stage 2: LL (ll0) + hi0, shared reads ----------------
    for (int e = tid; e < 69 * 19; e += 256) {
        int r = e / 19, w = e - r * 19;
        int ro = r * 20, r1 = ro + 20;
        float o0 = sm[XO + ro + w], e0 = sm[XE + ro + w + 1];
        float o1 = sm[XO + r1 + w], e1 = sm[XE + r1 + w + 1];

        // LLO point (odd col cO = j0-3+2w, and cO+1)
        float sA = o0 + e0, dA = o0 - e0;
        float sB = o1 + e1, dB = o1 - e1;
        sm[LLO + ro + w] = 0.25f * (sA + sB);
        bool hrow = (r >= 2) && (r <= 66);
        int hb = (r - 2) * 20;
        if (hrow && w >= 1 && w <= 17)
            sm[HSO + hb + (w - 1)] =
                0.25f * (fabsf(sA - sB) + fabsf(dA + dB) + fabsf(dA - dB));

        if (w <= 17) {
            float p0 = sm[XO + ro + w + 1];
            float p1 = sm[XO + r1 + w + 1];
            // LLE point (even col cE = j0-2+2w, and cE+1)
            float sC = e0 + p0, dC = e0 - p0;
            float sD = e1 + p1, dD = e1 - p1;
            sm[LLE + ro + w] = 0.25f * (sC + sD);
            if (hrow && w >= 1)
                sm[HSE + hb + (w - 1)] =
                    0.25f * (fabsf(sC - sD) + fabsf(dC + dD) + fabsf(dC - dD));
        }
    }
    __syncthreads();

    // ---------------- stage 3: ll1 / hi1 (writes alias dead xs region) ----------------
    const int A0 = (i0 >> 1) - 1;
    const int B0 = (j0 >> 1) - 1;
    float2* l12 = reinterpret_cast<float2*>(sm + L12);
    for (int e = tid; e < 34 * 18; e += 256) {
        int u = e / 18, v = e - u * 18;
        int a = clampi(A0 + u, 0, 127);
        int b = clampi(B0 + v, 0, 127);
        int d = b - B0;
        int rm = (clampi(2 * a - 1, 0, 254) - (i0 - 3)) * 20;
        int r0 = (2 * a - (i0 - 3)) * 20;
        int rp = (clampi(2 * a + 1, 0, 254) - (i0 - 3)) * 20;

        float m_m = sm[LLO + rm + d], m_0 = sm[LLE + rm + d], m_p = sm[LLO + rm + d + 1];
        float c_m = sm[LLO + r0 + d], c_0 = sm[LLE + r0 + d], c_p = sm[LLO + r0 + d + 1];
        float p_m = sm[LLO + rp + d], p_0 = sm[LLE + rp + d], p_p = sm[LLO + rp + d + 1];

        float wy0 = (2 * a + 0.5f) * INV256, wy1 = (2 * a + 1.5f) * INV256;
        float wx0 = (2 * b + 0.5f) * INV256, wx1 = (2 * b + 1.5f) * INV256;

        float Am = wx0 * m_m + (1.0f - wx0) * m_0;
        float Ac = wx0 * c_m + (1.0f - wx0) * c_0;
        float Ap = wx0 * p_m + (1.0f - wx0) * p_0;
        float Bm = wx1 * m_0 + (1.0f - wx1) * m_p;
        float Bc = wx1 * c_0 + (1.0f - wx1) * c_p;
        float Bp = wx1 * p_0 + (1.0f - wx1) * p_p;

        float L00 = wy0 * Am + (1.0f - wy0) * Ac;
        float L01 = wy0 * Bm + (1.0f - wy0) * Bc;
        float L10 = wy1 * Ac + (1.0f - wy1) * Ap;
        float L11 = wy1 * Bc + (1.0f - wy1) * Bp;

        float ll = 0.25f * (L00 + L01 + L10 + L11);
        float lh = 0.25f * (L00 + L01 - L10 - L11);
        float hl = 0.25f * (L00 - L01 + L10 - L11);
        float hh = 0.25f * (L00 - L01 - L10 + L11);
        l12[u * 18 + v] = make_float2(ll, fabsf(lh) + fabsf(hl) + fabsf(hh));
    }
    __syncthreads();

    // ---------------- stage 4: epilogue (2 vertical quads / thread) ----------------
    const int qx = tid & 15;
    const int ph = tid >> 4;                 // 0..15
    const int q = (j0 >> 1) + qx;            // out cols 2q, 2q+1
    const int p0 = (i0 >> 1) + 2 * ph;       // out rows 2p0..2p0+3

    // --- hi0 resize (255->256): 5 rows x 3 cols, 2 row clamps ---
    int s0 = (clampi(2 * p0 - 1, 0, 254) - (i0 - 1)) * 20;
    int s1 = (4 * ph + 1) * 20;
    int s2 = s1 + 20, s3 = s1 + 40;
    int s4 = (clampi(2 * p0 + 3, 0, 254) - (i0 - 1)) * 20;

    float w0 = (2 * q + 0.5f) * INV256;
    float w1 = (2 * q + 1.5f) * INV256;

#define HCL(S, CA, CB)                                                        \
    {                                                                         \
        float ov = sm[HSO + (S) + qx], ev = sm[HSE + (S) + qx];               \
        float o2 = sm[HSO + (S) + qx + 1];                                    \
        CA = w0 * ov + (1.0f - w0) * ev;                                      \
        CB = w1 * ev + (1.0f - w1) * o2;                                      \
    }
    float cA0, cB0, cA1, cB1, cA2, cB2, cA3, cB3, cA4, cB4;
    HCL(s0, cA0, cB0) HCL(s1, cA1, cB1) HCL(s2, cA2, cB2)
    HCL(s3, cA3, cB3) HCL(s4, cA4, cB4)
#undef HCL

    float wy0 = (2 * p0 + 0.5f) * INV256;
    float wy1 = (2 * p0 + 1.5f) * INV256;
    float wy2 = (2 * p0 + 2.5f) * INV256;
    float wy3 = (2 * p0 + 3.5f) * INV256;

    float h0A0 = wy0 * cA0 + (1.0f - wy0) * cA1;
    float h0B0 = wy0 * cB0 + (1.0f - wy0) * cB1;
    float h0A1 = wy1 * cA1 + (1.0f - wy1) * cA2;
    float h0B1 = wy1 * cB1 + (1.0f - wy1) * cB2;
    float h0A2 = wy2 * cA2 + (1.0f - wy2) * cA3;
    float h0B2 = wy2 * cB2 + (1.0f - wy2) * cB3;
    float h0A3 = wy3 * cA3 + (1.0f - wy3) * cA4;
    float h0B3 = wy3 * cB3 + (1.0f - wy3) * cB4;

    // --- ll1/hi1 resize (128->256): float2 taps, 4 rows x 3 cols, pure ---
    const float2* l12c = reinterpret_cast<const float2*>(sm + L12);
    int t0 = 2 * ph * 18 + qx;
    int t1 = t0 + 18, t2 = t0 + 36, t3 = t0 + 54;

#define LERP2(O, WA, A, WB, B)                                                \
    { O.x = (WA) * A.x + (WB) * B.x; O.y = (WA) * A.y + (WB) * B.y; }

    float2 r0m = l12c[t0], r0c = l12c[t0 + 1], r0p = l12c[t0 + 2];
    float2 r1m = l12c[t1], r1c = l12c[t1 + 1], r1p = l12c[t1 + 2];
    float2 r2m = l12c[t2], r2c = l12c[t2 + 1], r2p = l12c[t2 + 2];
    float2 r3m = l12c[t3], r3c = l12c[t3 + 1], r3p = l12c[t3 + 2];

    float2 a0, b0, a1, b1, a2, b2, a3, b3;
    LERP2(a0, 0.25f, r0m, 0.75f, r0c) LERP2(b0, 0.75f, r0c, 0.25f, r0p)
    LERP2(a1, 0.25f, r1m, 0.75f, r1c) LERP2(b1, 0.75f, r1c, 0.25f, r1p)
    LERP2(a2, 0.25f, r2m, 0.75f, r2c) LERP2(b2, 0.75f, r2c, 0.25f, r2p)
    LERP2(a3, 0.25f, r3m, 0.75f, r3c) LERP2(b3, 0.75f, r3c, 0.25f, r3p)

    float2 vA0, vB0, vA1, vB1, vA2, vB2, vA3, vB3;
    LERP2(vA0, 0.25f, a0, 0.75f, a1) LERP2(vB0, 0.25f, b0, 0.75f, b1)
    LERP2(vA1, 0.75f, a1, 0.25f, a2) LERP2(vB1, 0.75f, b1, 0.25f, b2)
    LERP2(vA2, 0.25f, a1, 0.75f, a2) LERP2(vB2, 0.25f, b1, 0.75f, b2)
    LERP2(vA3, 0.75f, a2, 0.25f, a3) LERP2(vB3, 0.75f, b2, 0.25f, b3)
#undef LERP2

    // --- stores: rows 2p0..2p0+3, cols 2q..2q+1 ---
    const size_t nimg = (size_t)nc * IMG;
    float* out_low = out;
    float* out_high = out + nimg;
    size_t base = (size_t)ch * IMG + (size_t)(2 * p0) * HW + 2 * q;

    *reinterpret_cast<float2*>(out_low + base) = make_float2(vA0.x, vB0.x);
    *reinterpret_cast<float2*>(out_low + base + HW) = make_float2(vA1.x, vB1.x);
    *reinterpret_cast<float2*>(out_low + base + 2 * HW) = make_float2(vA2.x, vB2.x);
    *reinterpret_cast<float2*>(out_low + base + 3 * HW) = make_float2(vA3.x, vB3.x);
    *reinterpret_cast<float2*>(out_high + base) =
        make_float2(0.5f * (h0A0 + vA0.y), 0.5f * (h0B0 + vB0.y));
    *reinterpret_cast<float2*>(out_high + base + HW) =
        make_float2(0.5f * (h0A1 + vA1.y), 0.5f * (h0B1 + vB1.y));
    *reinterpret_cast<float2*>(out_high + base + 2 * HW) =
        make_float2(0.5f * (h0A2 + vA2.y), 0.5f * (h0B2 + vB2.y));
    *reinterpret_cast<float2*>(out_high + base + 3 * HW) =
        make_float2(0.5f * (h0A3 + vA3.y), 0.5f * (h0B3 + vB3.y));
}

extern "C" void kernel_launch(void* const* d_in, const int* in_sizes, int n_in,
                              void* d_out, int out_size) {
    const float* x = (const float*)d_in[0];
    float* out = (float*)d_out;
    int nc = in_sizes[0] / IMG;  // 512

    dim3 blk(256);
    dim3 grd(HW / 32, HW / 64, nc);
    k_fused<<<grd, blk>>>(x, out, nc);
}

// round 13
// speedup vs baseline: 1.5384x; 1.0021x over previous
#include <cuda_runtime.h>

// HaarWavelet2D level=2, x:(8,64,256,256) fp32 -> (low,high).
// One fused kernel, 64x32 output tile per 256-thread block.
// E/O column-split smem (conflict-free stride-2), clamp-at-load + reflect
// patch for pure downstream indexing. ll1/hi1 interleaved float2 (LDS.64),
// OVERLAID on the xs region (dead after stage 2) -> 32.8KB smem, 7 CTAs/SM.
// Stage 1 uses float2 global loads on interior block columns.
//
// XE: even cols j0-4..j0+34 -> slots 0..19 (slot (c-j0+4)/2), stride 20
// XO: odd  cols j0-3..j0+35 -> slots 0..19 (slot (c-j0+3)/2), stride 20

#define HW 256
#define IMG (HW*HW)
#define INV256 (1.0f/256.0f)

// smem offsets (floats). XO-XE = 1424 ≡ 16 (mod 32).
#define XE 0
#define XO 1424
#define LLE 2848
#define LLO 4228
#define HSE 5608
#define HSO 6908
#define L12 0              // interleaved {ll1,hi1} float2, ALIASES xs region
#define SM_TOT 8208

__device__ __forceinline__ int clampi(int v, int lo, int hi) {
    return v < lo ? lo : (v > hi ? hi : v);
}

__global__ void __launch_bounds__(256, 7) k_fused(const float* __restrict__ x,
                                                  float* __restrict__ out, int nc) {
    __shared__ float sm[SM_TOT];

    const int ch = blockIdx.z;
    const int i0 = blockIdx.y * 64;
    const int j0 = blockIdx.x * 32;
    const int tid = threadIdx.x;
    const float* xc = x + (size_t)ch * IMG;

    // ---------------- stage 1: load x ----------------
    if (blockIdx.x != 0 && blockIdx.x != 7) {
        // interior: cols j0-4..j0+35 all in [0,255]; float2 loads (8B aligned).
        for (int e = tid; e < 70 * 20; e += 256) {
            int u = e / 20, m = e - u * 20;
            int gr = clampi(i0 - 3 + u, 0, 255);
            float2 v2 = *reinterpret_cast<const float2*>(xc + gr * HW + (j0 - 4 + 2 * m));
            sm[XE + u * 20 + m] = v2.x;   // even col j0-4+2m
            sm[XO + u * 20 + m] = v2.y;   // odd  col j0-3+2m
        }
    } else {
        // edge blocks: scalar with clamp + reflect patch.
        for (int e = tid; e < 70 * 38; e += 256) {
            int u = e / 38, v = e - u * 38;
            int gr = clampi(i0 - 3 + u, 0, 255);
            int g = j0 - 3 + v;
            int gc = clampi(g, 0, 255);
            if (g == -1) gc = 1;
            if (g == 256) gc = 254;
            float val = __ldg(xc + gr * HW + gc);
            // v odd -> even col g -> XE slot (v>>1)+1 ; v even -> odd col -> XO slot v>>1
            sm[((v & 1) ? (XE + 1) : XO) + u * 20 + (v >> 1)] = val;
        }
    }
    __syncthreads();

    // ---------------- stage 2: LL (ll0) + hi0, shared reads ----------------
    for (int e = tid; e < 69 * 19; e += 256) {
        int r = e / 19, w = e - r * 19;
        int ro = r * 20, r1 = ro + 20;
        float o0 = sm[XO + ro + w], e0 = sm[XE + ro + w + 1];
        float o1 = sm[XO + r1 + w], e1 = sm[XE + r1 + w + 1];

        // LLO point (odd col cO = j0-3+2w, and cO+1)
        float sA = o0 + e0, dA = o0 - e0;
        float sB = o1 + e1, dB = o1 - e1;
        sm[LLO + ro + w] = 0.25f * (sA + sB);
        bool hrow = (r >= 2) && (r <= 66);
        int hb = (r - 2) * 20;
        if (hrow && w >= 1 && w <= 17)
            sm[HSO + hb + (w - 1)] =
                0.25f * (fabsf(sA - sB) + fabsf(dA + dB) + fabsf(dA - dB));

        if (w <= 17) {
            float p0 = sm[XO + ro + w + 1];
            float p1 = sm[XO + r1 + w + 1];
            // LLE point (even col cE = j0-2+2w, and cE+1)
            float sC = e0 + p0, dC = e0 - p0;
            float sD = e1 + p1, dD = e1 - p1;
            sm[LLE + ro + w] = 0.25f * (sC + sD);
            if (hrow && w >= 1)
                sm[HSE + hb + (w - 1)] =
                    0.25f * (fabsf(sC - sD) + fabsf(dC + dD) + fabsf(dC - dD));
        }
    }
    __syncthreads();

    // ---------------- stage 3: ll1 / hi1 (writes alias dead xs region) ----------------
    const int A0 = (i0 >> 1) - 1;
    const int B0 = (j0 >> 1) - 1;
    float2* l12 = reinterpret_cast<float2*>(sm + L12);
    for (int e = tid; e < 34 * 18; e += 256) {
        int u = e / 18, v = e - u * 18;
        int a = clampi(A0 + u, 0, 127);
        int b = clampi(B0 + v, 0, 127);
        int d = b - B0;
        int rm = (clampi(2 * a - 1, 0, 254) - (i0 - 3)) * 20;
        int r0 = (2 * a - (i0 - 3)) * 20;
        int rp = (clampi(2 * a + 1, 0, 254) - (i0 - 3)) * 20;

        float m_m = sm[LLO + rm + d], m_0 = sm[LLE + rm + d], m_p = sm[LLO + rm + d + 1];
        float c_m = sm[LLO + r0 + d], c_0 = sm[LLE + r0 + d], c_p = sm[LLO + r0 + d + 1];
        float p_m = sm[LLO + rp + d], p_0 = sm[LLE + rp + d], p_p = sm[LLO + rp + d + 1];

        float wy0 = (2 * a + 0.5f) * INV256, wy1 = (2 * a + 1.5f) * INV256;
        float wx0 = (2 * b + 0.5f) * INV256, wx1 = (2 * b + 1.5f) * INV256;

        float Am = wx0 * m_m + (1.0f - wx0) * m_0;
        float Ac = wx0 * c_m + (1.0f - wx0) * c_0;
        float Ap = wx0 * p_m + (1.0f - wx0) * p_0;
        float Bm = wx1 * m_0 + (1.0f - wx1) * m_p;
        float Bc = wx1 * c_0 + (1.0f - wx1) * c_p;
        float Bp = wx1 * p_0 + (1.0f - wx1) * p_p;

        float L00 = wy0 * Am + (1.0f - wy0) * Ac;
        float L01 = wy0 * Bm + (1.0f - wy0) * Bc;
        float L10 = wy1 * Ac + (1.0f - wy1) * Ap;
        float L11 = wy1 * Bc + (1.0f - wy1) * Bp;

        float ll = 0.25f * (L00 + L01 + L10 + L11);
        float lh = 0.25f * (L00 + L01 - L10 - L11);
        float hl = 0.25f * (L00 - L01 + L10 - L11);
        float hh = 0.25f * (L00 - L01 - L10 + L11);
        l12[u * 18 + v] = make_float2(ll, fabsf(lh) + fabsf(hl) + fabsf(hh));
    }
    __syncthreads();

    // ---------------- stage 4: epilogue (2 vertical quads / thread) ----------------
    const int qx = tid & 15;
    const int ph = tid >> 4;                 // 0..15
    const int q = (j0 >> 1) + qx;            // out cols 2q, 2q+1
    const int p0 = (i0 >> 1) + 2 * ph;       // out rows 2p0..2p0+3

    // --- hi0 resize (255->256): 5 rows x 3 cols, 2 row clamps ---
    int s0 = (clampi(2 * p0 - 1, 0, 254) - (i0 - 1)) * 20;
    int s1 = (4 * ph + 1) * 20;
    int s2 = s1 + 20, s3 = s1 + 40;
    int s4 = (clampi(2 * p0 + 3, 0, 254) - (i0 - 1)) * 20;

    float w0 = (2 * q + 0.5f) * INV256;
    float w1 = (2 * q + 1.5f) * INV256;

#define HCL(S, CA, CB)                                                        \
    {                                                                         \
        float ov = sm[HSO + (S) + qx], ev = sm[HSE + (S) + qx];               \
        float o2 = sm[HSO + (S) + qx + 1];                                    \
        CA = w0 * ov + (1.0f - w0) * ev;                                      \
        CB = w1 * ev + (1.0f - w1) * o2;                                      \
    }
    float cA0, cB0, cA1, cB1, cA2, cB2, cA3, cB3, cA4, cB4;
    HCL(s0, cA0, cB0) HCL(s1, cA1, cB1) HCL(s2, cA2, cB2)
    HCL(s3, cA3, cB3) HCL(s4, cA4, cB4)
#undef HCL

    float wy0 = (2 * p0 + 0.5f) * INV256;
    float wy1 = (2 * p0 + 1.5f) * INV256;
    float wy2 = (2 * p0 + 2.5f) * INV256;
    float wy3 = (2 * p0 + 3.5f) * INV256;

    float h0A0 = wy0 * cA0 + (1.0f - wy0) * cA1;
    float h0B0 = wy0 * cB0 + (1.0f - wy0) * cB1;
    float h0A1 = wy1 * cA1 + (1.0f - wy1) * cA2;
    float h0B1 = wy1 * cB1 + (1.0f - wy1) * cB2;
    float h0A2 = wy2 * cA2 + (1.0f - wy2) * cA3;
    float h0B2 = wy2 * cB2 + (1.0f - wy2) * cB3;
    float h0A3 = wy3 * cA3 + (1.0f - wy3) * cA4;
    float h0B3 = wy3 * cB3 + (1.0f - wy3) * cB4;

    // --- ll1/hi1 resize (128->256): float2 taps, 4 rows x 3 cols, pure ---
    const float2* l12c = reinterpret_cast<const float2*>(sm + L12);
    int t0 = 2 * ph * 18 + qx;
    int t1 = t0 + 18, t2 = t0 + 36, t3 = t0 + 54;

#define LERP2(O, WA, A, WB, B)                                                \
    { O.x = (WA) * A.x + (WB) * B.x; O.y = (WA) * A.y + (WB) * B.y; }

    float2 r0m = l12c[t0], r0c = l12c[t0 + 1], r0p = l12c[t0 + 2];
    float2 r1m = l12c[t1], r1c = l12c[t1 + 1], r1p = l12c[t1 + 2];
    float2 r2m = l12c[t2], r2c = l12c[t2 + 1], r2p = l12c[t2 + 2];
    float2 r3m = l12c[t3], r3c = l12c[t3 + 1], r3p = l12c[t3 + 2];

    float2 a0, b0, a1, b1, a2, b2, a3, b3;
    LERP2(a0, 0.25f, r0m, 0.75f, r0c) LERP2(b0, 0.75f, r0c, 0.25f, r0p)
    LERP2(a1, 0.25f, r1m, 0.75f, r1c) LERP2(b1, 0.75f, r1c, 0.25f, r1p)
    LERP2(a2, 0.25f, r2m, 0.75f, r2c) LERP2(b2, 0.75f, r2c, 0.25f, r2p)
    LERP2(a3, 0.25f, r3m, 0.75f, r3c) LERP2(b3, 0.75f, r3c, 0.25f, r3p)

    float2 vA0, vB0, vA1, vB1, vA2, vB2, vA3, vB3;
    LERP2(vA0, 0.25f, a0, 0.75f, a1) LERP2(vB0, 0.25f, b0, 0.75f, b1)
    LERP2(vA1, 0.75f, a1, 0.25f, a2) LERP2(vB1, 0.75f, b1, 0.25f, b2)
    LERP2(vA2, 0.25f, a1, 0.75f, a2) LERP2(vB2, 0.25f, b1, 0.75f, b2)
    LERP2(vA3, 0.75f, a2, 0.25f, a3) LERP2(vB3, 0.75f, b2, 0.25f, b3)
#undef LERP2

    // --- stores: rows 2p0..2p0+3, cols 2q..2q+1 ---
    const size_t nimg = (size_t)nc * IMG;
    float* out_low = out;
    float* out_high = out + nimg;
    size_t base = (size_t)ch * IMG + (size_t)(2 * p0) * HW + 2 * q;

    *reinterpret_cast<float2*>(out_low + base) = make_float2(vA0.x, vB0.x);
    *reinterpret_cast<float2*>(out_low + base + HW) = make_float2(vA1.x, vB1.x);
    *reinterpret_cast<float2*>(out_low + base + 2 * HW) = make_float2(vA2.x, vB2.x);
    *reinterpret_cast<float2*>(out_low + base + 3 * HW) = make_float2(vA3.x, vB3.x);
    *reinterpret_cast<float2*>(out_high + base) =
        make_float2(0.5f * (h0A0 + vA0.y), 0.5f * (h0B0 + vB0.y));
    *reinterpret_cast<float2*>(out_high + base + HW) =
        make_float2(0.5f * (h0A1 + vA1.y), 0.5f * (h0B1 + vB1.y));
    *reinterpret_cast<float2*>(out_high + base + 2 * HW) =
        make_float2(0.5f * (h0A2 + vA2.y), 0.5f * (h0B2 + vB2.y));
    *reinterpret_cast<float2*>(out_high + base + 3 * HW) =
        make_float2(0.5f * (h0A3 + vA3.y), 0.5f * (h0B3 + vB3.y));
}

extern "C" void kernel_launch(void* const* d_in, const int* in_sizes, int n_in,
                              void* d_out, int out_size) {
    const float* x = (const float*)d_in[0];
    float* out = (float*)d_out;
    int nc = in_sizes[0] / IMG;  // 512

    dim3 blk(256);
    dim3 grd(HW / 32, HW / 64, nc);
    k_fused<<<grd, blk>>>(x, out, nc);
}